// round 11
// baseline (speedup 1.0000x reference)
#include <cuda_runtime.h>
#include <cuda_fp16.h>
#include <math.h>

#define NN 100000
#define EE 3200000
#define BB 1000
#define FIN 128
#define SF 12         // fp32 row stride for p
#define SH 16         // fp16 row stride (layer-1 message/accumulator): 32B
#define SW 8          // fp32 stride for s2w: 32B -> private L2 sector per node
#define XPAD 36       // smem x-stage row stride (floats): 144B, 16B-aligned, conflict-free

// Scratch (static device globals: no allocation anywhere)
__device__ float    g_p  [NN * SF];   // x @ W1[0:128]               (fp32)
__device__ __half   g_y  [NN * SH];   // x @ W1[128:256], slot10=1.0 (fp16 message)
__device__ __half   g_s1 [NN * SH];   // edge-accumulated y (slot10 = in-degree)
__device__ float    g_zw [NN];        // scalar layer-2 message  zω = h·(W2b@Wfc)
__device__ float    g_s2w[NN * SW];   // edge-accumulated zω (padded: 1 sector/node)
__device__ float2   g_qi [NN];        // {qω = h·(W2a@Wfc), 1/max(deg,1)}
__device__ float    g_g  [BB * 2];    // {Σ h2ω, node count} per graph
__device__ unsigned g_cnt;            // block-completion counter for fused pool+head

__device__ __forceinline__ void red_add_v2_f32(float* p, float a, float b) {
    asm volatile("red.global.add.v2.f32 [%0], {%1,%2};"
                 :: "l"(p), "f"(a), "f"(b) : "memory");
}
__device__ __forceinline__ void red_add_f32(float* p, float a) {
    asm volatile("red.global.add.f32 [%0], %1;" :: "l"(p), "f"(a) : "memory");
}
__device__ __forceinline__ void red_add_v4_h2(void* p, unsigned a, unsigned b, unsigned c, unsigned d) {
    asm volatile("red.global.add.noftz.v4.f16x2 [%0], {%1,%2,%3,%4};"
                 :: "l"(p), "r"(a), "r"(b), "r"(c), "r"(d) : "memory");
}
__device__ __forceinline__ void red_add_v2_h2(void* p, unsigned a, unsigned b) {
    asm volatile("red.global.add.noftz.v2.f16x2 [%0], {%1,%2};"
                 :: "l"(p), "r"(a), "r"(b) : "memory");
}

__device__ __forceinline__ unsigned pack_h2(float lo, float hi) {
    __half2 h = __floats2half2_rn(lo, hi);
    return *(unsigned*)&h;
}
__device__ __forceinline__ unsigned long long pack_f32x2(float lo, float hi) {
    unsigned long long r;
    asm("mov.b64 %0, {%1,%2};" : "=l"(r) : "f"(lo), "f"(hi));
    return r;
}
__device__ __forceinline__ void unpack_f32x2(float& lo, float& hi, unsigned long long v) {
    asm("mov.b64 {%0,%1}, %2;" : "=f"(lo), "=f"(hi) : "l"(v));
}
__device__ __forceinline__ void fma_f32x2(unsigned long long& acc,
                                          unsigned long long a, unsigned long long b) {
    asm("fma.rn.f32x2 %0, %1, %2, %0;" : "+l"(acc) : "l"(a), "l"(b));
}

// ---------------------------------------------------------------------------
// K1: p = x @ W1[0:128,:] (fp32), y = x @ W1[128:256,:] (fp16, slot10=1.0)
// Coalesced: x rows staged through padded smem per 32-float feature chunk.
// Also zeroes g_s1 / g_s2w rows, g_g, and g_cnt.
// ---------------------------------------------------------------------------
__global__ __launch_bounds__(256) void k1_project(const float* __restrict__ x,
                                                  const float* __restrict__ W1) {
    __shared__ __align__(16) float sW[2 * FIN * 10];   // 10,240 B
    __shared__ __align__(16) float sX[256 * XPAD];     // 36,864 B
    int tid = threadIdx.x;
    for (int i = tid; i < 2 * FIN * 10; i += 256) sW[i] = W1[i];

    int base = blockIdx.x * 256;
    int n = base + tid;
    bool valid = (n < NN);

    if (valid) {
        if (n == 0) g_cnt = 0u;
        uint4 zz = {0, 0, 0, 0};
        uint4* s1r = (uint4*)(g_s1 + (size_t)n * SH);
        s1r[0] = zz; s1r[1] = zz;
        uint4* s2r = (uint4*)(g_s2w + (size_t)n * SW);
        s2r[0] = zz; s2r[1] = zz;
        if (n < BB) { g_g[2 * n] = 0.f; g_g[2 * n + 1] = 0.f; }
    }

    unsigned long long accP[5], accY[5];
#pragma unroll
    for (int j = 0; j < 5; j++) { accP[j] = 0ull; accY[j] = 0ull; }

    for (int c = 0; c < FIN / 32; c++) {           // 4 chunks of 32 features
        __syncthreads();                            // protect prior-chunk reads
        // stage: 256 rows x 32 floats, fully coalesced float4 LDGs
#pragma unroll
        for (int i = 0; i < 8; i++) {
            int idx = tid + i * 256;                // float4 slot in chunk
            int nd  = idx >> 3;                     // node-in-block
            int jo  = (idx & 7) * 4;                // float offset in chunk
            int gn  = base + nd; if (gn >= NN) gn = NN - 1;
            float4 v = *(const float4*)(x + (size_t)gn * FIN + c * 32 + jo);
            *(float4*)&sX[nd * XPAD + jo] = v;
        }
        __syncthreads();

        const float* xr = &sX[tid * XPAD];
#pragma unroll
        for (int half = 0; half < 2; half++) {
            float4 xq[4];
#pragma unroll
            for (int i = 0; i < 4; i++)
                xq[i] = *(const float4*)&xr[half * 16 + i * 4];
            float xs[16];
#pragma unroll
            for (int i = 0; i < 4; i++) {
                xs[4 * i + 0] = xq[i].x; xs[4 * i + 1] = xq[i].y;
                xs[4 * i + 2] = xq[i].z; xs[4 * i + 3] = xq[i].w;
            }
#pragma unroll
            for (int j = 0; j < 16; j++) {
                int f = c * 32 + half * 16 + j;
                unsigned long long bx = pack_f32x2(xs[j], xs[j]);
                const unsigned long long* wp = (const unsigned long long*)&sW[f * 10];
                const unsigned long long* wy = (const unsigned long long*)&sW[(FIN + f) * 10];
#pragma unroll
                for (int jj = 0; jj < 5; jj++) {
                    fma_f32x2(accP[jj], bx, wp[jj]);
                    fma_f32x2(accY[jj], bx, wy[jj]);
                }
            }
        }
    }

    if (!valid) return;

    float* pr = g_p + (size_t)n * SF;
    float yv[10];
#pragma unroll
    for (int j = 0; j < 5; j++) {
        float lo, hi;
        unpack_f32x2(lo, hi, accP[j]);
        pr[2 * j] = lo; pr[2 * j + 1] = hi;
        unpack_f32x2(yv[2 * j], yv[2 * j + 1], accY[j]);
    }

    uint4 u0, u1;
    u0.x = pack_h2(yv[0], yv[1]);
    u0.y = pack_h2(yv[2], yv[3]);
    u0.z = pack_h2(yv[4], yv[5]);
    u0.w = pack_h2(yv[6], yv[7]);
    u1.x = pack_h2(yv[8], yv[9]);
    u1.y = pack_h2(1.0f, 0.0f);     // degree carrier
    u1.z = 0; u1.w = 0;
    uint4* yr = (uint4*)(g_y + (size_t)n * SH);
    yr[0] = u0; yr[1] = u1;
}

// ---------------------------------------------------------------------------
// K2: layer-1 edge scatter fp16 (2 REDs/edge), 4 edges per thread. PDL entry.
// ---------------------------------------------------------------------------
__global__ void k_edge_scatter1(const int* __restrict__ src, const int* __restrict__ dst,
                                const __half* __restrict__ msg, __half* __restrict__ acc) {
    cudaGridDependencySynchronize();
    int t = blockIdx.x * blockDim.x + threadIdx.x;   // t in [0, EE/4)
    int4 s4 = ((const int4*)src)[t];
    int4 d4 = ((const int4*)dst)[t];
    int ss[4] = {s4.x, s4.y, s4.z, s4.w};
    int dd[4] = {d4.x, d4.y, d4.z, d4.w};

    uint4 a[4]; uint2 b[4];
#pragma unroll
    for (int k = 0; k < 4; k++) {
        const uint4* v = (const uint4*)(msg + (size_t)ss[k] * SH);
        a[k] = v[0];
        b[k] = ((const uint2*)v)[2];
    }
#pragma unroll
    for (int k = 0; k < 4; k++) {
        __half* o = acc + (size_t)dd[k] * SH;
        red_add_v4_h2(o,     a[k].x, a[k].y, a[k].z, a[k].w);
        red_add_v2_h2(o + 8, b[k].x, b[k].y);
    }
}

// ---------------------------------------------------------------------------
// K3: h = relu(p + s1/deg); qω = h·(W2a@Wfc); zω = h·(W2b@Wfc). PDL entry.
// ---------------------------------------------------------------------------
__global__ void k3_layer2in(const float* __restrict__ W2, const float* __restrict__ Wfc) {
    cudaGridDependencySynchronize();
    __shared__ float sWa[10], sWb[10];
    if (threadIdx.x < 20) {
        int k = threadIdx.x;            // row of W2 [20 x 10]
        float v = 0.f;
#pragma unroll
        for (int j = 0; j < 10; j++) v += W2[k * 10 + j] * Wfc[j];
        if (k < 10) sWa[k] = v; else sWb[k - 10] = v;
    }
    __syncthreads();

    int n = blockIdx.x * blockDim.x + threadIdx.x;
    if (n >= NN) return;

    const float* pr = g_p + (size_t)n * SF;
    const uint4* sv = (const uint4*)(g_s1 + (size_t)n * SH);
    uint4 a = sv[0];
    uint2 b = ((const uint2*)sv)[2];

    float s[12];
    {
        float2 t;
        t = __half22float2(*(__half2*)&a.x); s[0] = t.x; s[1] = t.y;
        t = __half22float2(*(__half2*)&a.y); s[2] = t.x; s[3] = t.y;
        t = __half22float2(*(__half2*)&a.z); s[4] = t.x; s[5] = t.y;
        t = __half22float2(*(__half2*)&a.w); s[6] = t.x; s[7] = t.y;
        t = __half22float2(*(__half2*)&b.x); s[8] = t.x; s[9] = t.y;
        t = __half22float2(*(__half2*)&b.y); s[10] = t.x; s[11] = t.y;
    }
    float inv = 1.f / fmaxf(s[10], 1.f);

    float qw = 0.f, zw = 0.f;
#pragma unroll
    for (int j = 0; j < 10; j++) {
        float h = fmaxf(pr[j] + s[j] * inv, 0.f);
        qw += h * sWa[j];
        zw += h * sWb[j];
    }

    g_zw[n] = zw;
    g_qi[n] = make_float2(qw, inv);
}

// ---------------------------------------------------------------------------
// K4: layer-2 edge scatter — ONE scalar fp32 RED per edge to a PRIVATE sector.
// PDL entry.
// ---------------------------------------------------------------------------
__global__ void k_edge_scatter2(const int* __restrict__ src, const int* __restrict__ dst) {
    cudaGridDependencySynchronize();
    int t = blockIdx.x * blockDim.x + threadIdx.x;   // t in [0, EE/4)
    int4 s4 = ((const int4*)src)[t];
    int4 d4 = ((const int4*)dst)[t];
    float v0 = g_zw[s4.x];
    float v1 = g_zw[s4.y];
    float v2 = g_zw[s4.z];
    float v3 = g_zw[s4.w];
    red_add_f32(&g_s2w[(size_t)d4.x * SW], v0);
    red_add_f32(&g_s2w[(size_t)d4.y * SW], v1);
    red_add_f32(&g_s2w[(size_t)d4.z * SW], v2);
    red_add_f32(&g_s2w[(size_t)d4.w * SW], v3);
}

// ---------------------------------------------------------------------------
// K5 (fused with head): h2ω = qω + s2ω/deg; segmented warp-reduce over sorted
// batch; head lanes RED into g_g[b]. Last block computes the sigmoid outputs.
// PDL entry.
// ---------------------------------------------------------------------------
__global__ void k5_pool_head(const int* __restrict__ batch, float* __restrict__ out) {
    cudaGridDependencySynchronize();
    int n = blockIdx.x * blockDim.x + threadIdx.x;
    int lane = threadIdx.x & 31;

    int b = -1;
    float v = 0.f, c = 0.f;
    if (n < NN) {
        float2 qi = g_qi[n];
        v = qi.x + g_s2w[(size_t)n * SW] * qi.y;
        c = 1.f;
        b = batch[n];
    }

    // segmented suffix sum over contiguous equal-b runs (batch sorted)
#pragma unroll
    for (int off = 1; off < 32; off <<= 1) {
        float v2 = __shfl_down_sync(0xffffffff, v, off);
        float c2 = __shfl_down_sync(0xffffffff, c, off);
        int   b2 = __shfl_down_sync(0xffffffff, b, off);
        if (lane + off < 32 && b2 == b) { v += v2; c += c2; }
    }
    int bprev = __shfl_up_sync(0xffffffff, b, 1);
    bool head = (lane == 0) || (bprev != b);
    if (head && b >= 0)
        red_add_v2_f32(&g_g[2 * b], v, c);

    // last-block head: all pool REDs are visible after the counter round-trip
    __threadfence();
    __shared__ bool isLast;
    if (threadIdx.x == 0) {
        unsigned prev = atomicAdd(&g_cnt, 1u);
        isLast = (prev == gridDim.x - 1);
    }
    __syncthreads();
    if (isLast) {
        __threadfence();
        for (int bb = threadIdx.x; bb < BB; bb += blockDim.x) {
            float sum = g_g[2 * bb];
            float cnt = g_g[2 * bb + 1];
            float vv = sum / fmaxf(cnt, 1.f);
            out[bb] = 1.f / (1.f + expf(-vv));
        }
    }
}

// ---------------------------------------------------------------------------
extern "C" void kernel_launch(void* const* d_in, const int* in_sizes, int n_in,
                              void* d_out, int out_size) {
    const float* x     = (const float*)d_in[0];
    const int*   ei    = (const int*)  d_in[1];   // src = ei[0:E), dst = ei[E:2E)
    const int*   batch = (const int*)  d_in[2];
    const float* W1    = (const float*)d_in[3];
    const float* W2    = (const float*)d_in[4];
    const float* Wfc   = (const float*)d_in[5];
    float*       out   = (float*)d_out;

    void *p_y, *p_s1;
    cudaGetSymbolAddress(&p_y,  g_y);
    cudaGetSymbolAddress(&p_s1, g_s1);
    const __half* yv  = (const __half*)p_y;
    __half*       s1v = (__half*)p_s1;

    const int T = 256;

    cudaLaunchAttribute pdl[1];
    pdl[0].id = cudaLaunchAttributeProgrammaticStreamSerialization;
    pdl[0].val.programmaticStreamSerializationAllowed = 1;

    k1_project<<<(NN + 255) / 256, 256>>>(x, W1);

    {
        cudaLaunchConfig_t cfg = {};
        cfg.gridDim = dim3(EE / 4 / T); cfg.blockDim = dim3(T);
        cfg.stream = 0; cfg.attrs = pdl; cfg.numAttrs = 1;
        const int* srcp = ei; const int* dstp = ei + EE;
        cudaLaunchKernelEx(&cfg, k_edge_scatter1, srcp, dstp, yv, s1v);
    }
    {
        cudaLaunchConfig_t cfg = {};
        cfg.gridDim = dim3((NN + 127) / 128); cfg.blockDim = dim3(128);
        cfg.stream = 0; cfg.attrs = pdl; cfg.numAttrs = 1;
        cudaLaunchKernelEx(&cfg, k3_layer2in, W2, Wfc);
    }
    {
        cudaLaunchConfig_t cfg = {};
        cfg.gridDim = dim3(EE / 4 / T); cfg.blockDim = dim3(T);
        cfg.stream = 0; cfg.attrs = pdl; cfg.numAttrs = 1;
        const int* srcp = ei; const int* dstp = ei + EE;
        cudaLaunchKernelEx(&cfg, k_edge_scatter2, srcp, dstp);
    }
    {
        cudaLaunchConfig_t cfg = {};
        cfg.gridDim = dim3((NN + T - 1) / T); cfg.blockDim = dim3(T);
        cfg.stream = 0; cfg.attrs = pdl; cfg.numAttrs = 1;
        cudaLaunchKernelEx(&cfg, k5_pool_head, batch, out);
    }
}

// round 12
// speedup vs baseline: 1.0471x; 1.0471x over previous
#include <cuda_runtime.h>
#include <cuda_fp16.h>
#include <math.h>

#define NN 100000
#define EE 3200000
#define BB 1000
#define FIN 128
#define SF 12         // fp32 row stride for p
#define SH 16         // fp16 row stride (layer-1 message/accumulator): 32B
#define SW 8          // fp32 stride for s2w: 32B -> private L2 sector per node
#define SWR 12        // padded smem weight row (floats): 48B, 16B-aligned

// Scratch (static device globals: no allocation anywhere)
__device__ float    g_p  [NN * SF];   // x @ W1[0:128]               (fp32)
__device__ __half   g_y  [NN * SH];   // x @ W1[128:256], slot10=1.0 (fp16 message)
__device__ __half   g_s1 [NN * SH];   // edge-accumulated y (slot10 = in-degree)
__device__ float    g_zw [NN];        // scalar layer-2 message  zω = h·(W2b@Wfc)
__device__ float    g_s2w[NN * SW];   // edge-accumulated zω (padded: 1 sector/node)
__device__ float2   g_qi [NN];        // {qω = h·(W2a@Wfc), 1/max(deg,1)}
__device__ float    g_g  [BB * 2];    // {Σ h2ω, node count} per graph
__device__ unsigned g_cnt;            // block-completion counter for fused pool+head

__device__ __forceinline__ void red_add_v2_f32(float* p, float a, float b) {
    asm volatile("red.global.add.v2.f32 [%0], {%1,%2};"
                 :: "l"(p), "f"(a), "f"(b) : "memory");
}
__device__ __forceinline__ void red_add_f32(float* p, float a) {
    asm volatile("red.global.add.f32 [%0], %1;" :: "l"(p), "f"(a) : "memory");
}
__device__ __forceinline__ void red_add_v4_h2(void* p, unsigned a, unsigned b, unsigned c, unsigned d) {
    asm volatile("red.global.add.noftz.v4.f16x2 [%0], {%1,%2,%3,%4};"
                 :: "l"(p), "r"(a), "r"(b), "r"(c), "r"(d) : "memory");
}
__device__ __forceinline__ void red_add_v2_h2(void* p, unsigned a, unsigned b) {
    asm volatile("red.global.add.noftz.v2.f16x2 [%0], {%1,%2};"
                 :: "l"(p), "r"(a), "r"(b) : "memory");
}

__device__ __forceinline__ unsigned pack_h2(float lo, float hi) {
    __half2 h = __floats2half2_rn(lo, hi);
    return *(unsigned*)&h;
}
__device__ __forceinline__ unsigned long long pack_f32x2(float lo, float hi) {
    unsigned long long r;
    asm("mov.b64 %0, {%1,%2};" : "=l"(r) : "f"(lo), "f"(hi));
    return r;
}
__device__ __forceinline__ void unpack_f32x2(float& lo, float& hi, unsigned long long v) {
    asm("mov.b64 {%0,%1}, %2;" : "=f"(lo), "=f"(hi) : "l"(v));
}
__device__ __forceinline__ void fma_f32x2(unsigned long long& acc,
                                          unsigned long long a, unsigned long long b) {
    asm("fma.rn.f32x2 %0, %1, %2, %0;" : "+l"(acc) : "l"(a), "l"(b));
}

// ---------------------------------------------------------------------------
// K1: p = x @ W1[0:128,:] (fp32), y = x @ W1[128:256,:] (fp16, slot10=1.0)
// 128 threads/block, 2 nodes/thread (tid, tid+128) -> 391 blocks (no wave tail).
// Weight rows padded to 48B so each feature needs 6 LDS (2x LDS.128 + LDS.64
// per output bank), shared across both nodes: 26 warp-instrs per feature per
// 2 nodes vs 40 before. Also zeroes g_s1/g_s2w rows, g_g, g_cnt.
// ---------------------------------------------------------------------------
__global__ __launch_bounds__(128) void k1_project(const float* __restrict__ x,
                                                  const float* __restrict__ W1) {
    __shared__ __align__(16) float sW[2 * FIN * SWR];   // 12,288 B
    int tid = threadIdx.x;
    for (int r = tid; r < 2 * FIN; r += 128) {
        const float* wsrc = W1 + r * 10;
        float* wdst = sW + r * SWR;
#pragma unroll
        for (int j = 0; j < 10; j++) wdst[j] = wsrc[j];
        wdst[10] = 0.f; wdst[11] = 0.f;
    }
    __syncthreads();

    int base = blockIdx.x * 256;
    int n1 = base + tid;
    int n2 = n1 + 128;
    bool v1 = (n1 < NN);
    bool v2 = (n2 < NN);

    // zero accumulators for this launch
    uint4 zz = {0, 0, 0, 0};
    if (v1) {
        if (n1 == 0) g_cnt = 0u;
        uint4* s1r = (uint4*)(g_s1 + (size_t)n1 * SH);
        s1r[0] = zz; s1r[1] = zz;
        uint4* s2r = (uint4*)(g_s2w + (size_t)n1 * SW);
        s2r[0] = zz; s2r[1] = zz;
        if (n1 < BB) { g_g[2 * n1] = 0.f; g_g[2 * n1 + 1] = 0.f; }
    }
    if (v2) {
        uint4* s1r = (uint4*)(g_s1 + (size_t)n2 * SH);
        s1r[0] = zz; s1r[1] = zz;
        uint4* s2r = (uint4*)(g_s2w + (size_t)n2 * SW);
        s2r[0] = zz; s2r[1] = zz;
        if (n2 < BB) { g_g[2 * n2] = 0.f; g_g[2 * n2 + 1] = 0.f; }
    }
    if (!v1) return;   // (v1 false implies v2 false)

    unsigned long long aP1[5], aY1[5], aP2[5], aY2[5];
#pragma unroll
    for (int j = 0; j < 5; j++) { aP1[j] = 0ull; aY1[j] = 0ull; aP2[j] = 0ull; aY2[j] = 0ull; }

    const float4* xr1 = (const float4*)(x + (size_t)n1 * FIN);
    const float4* xr2 = (const float4*)(x + (size_t)(v2 ? n2 : n1) * FIN);

#pragma unroll 2
    for (int f4 = 0; f4 < FIN / 4; f4++) {
        float4 xa = xr1[f4];
        float4 xb = xr2[f4];
        float xf1[4] = {xa.x, xa.y, xa.z, xa.w};
        float xf2[4] = {xb.x, xb.y, xb.z, xb.w};
#pragma unroll
        for (int k = 0; k < 4; k++) {
            int f = f4 * 4 + k;
            const ulonglong2* wpv = (const ulonglong2*)&sW[f * SWR];
            ulonglong2 wpA = wpv[0];
            ulonglong2 wpB = wpv[1];
            unsigned long long wpC = *(const unsigned long long*)&sW[f * SWR + 8];
            const ulonglong2* wyv = (const ulonglong2*)&sW[(FIN + f) * SWR];
            ulonglong2 wyA = wyv[0];
            ulonglong2 wyB = wyv[1];
            unsigned long long wyC = *(const unsigned long long*)&sW[(FIN + f) * SWR + 8];

            unsigned long long b1 = pack_f32x2(xf1[k], xf1[k]);
            unsigned long long b2 = pack_f32x2(xf2[k], xf2[k]);

            fma_f32x2(aP1[0], b1, wpA.x); fma_f32x2(aP1[1], b1, wpA.y);
            fma_f32x2(aP1[2], b1, wpB.x); fma_f32x2(aP1[3], b1, wpB.y);
            fma_f32x2(aP1[4], b1, wpC);
            fma_f32x2(aY1[0], b1, wyA.x); fma_f32x2(aY1[1], b1, wyA.y);
            fma_f32x2(aY1[2], b1, wyB.x); fma_f32x2(aY1[3], b1, wyB.y);
            fma_f32x2(aY1[4], b1, wyC);

            fma_f32x2(aP2[0], b2, wpA.x); fma_f32x2(aP2[1], b2, wpA.y);
            fma_f32x2(aP2[2], b2, wpB.x); fma_f32x2(aP2[3], b2, wpB.y);
            fma_f32x2(aP2[4], b2, wpC);
            fma_f32x2(aY2[0], b2, wyA.x); fma_f32x2(aY2[1], b2, wyA.y);
            fma_f32x2(aY2[2], b2, wyB.x); fma_f32x2(aY2[3], b2, wyB.y);
            fma_f32x2(aY2[4], b2, wyC);
        }
    }

    {
        float* pr = g_p + (size_t)n1 * SF;
        float yv[10];
#pragma unroll
        for (int j = 0; j < 5; j++) {
            float lo, hi;
            unpack_f32x2(lo, hi, aP1[j]);
            pr[2 * j] = lo; pr[2 * j + 1] = hi;
            unpack_f32x2(yv[2 * j], yv[2 * j + 1], aY1[j]);
        }
        uint4 u0, u1;
        u0.x = pack_h2(yv[0], yv[1]);
        u0.y = pack_h2(yv[2], yv[3]);
        u0.z = pack_h2(yv[4], yv[5]);
        u0.w = pack_h2(yv[6], yv[7]);
        u1.x = pack_h2(yv[8], yv[9]);
        u1.y = pack_h2(1.0f, 0.0f);     // degree carrier
        u1.z = 0; u1.w = 0;
        uint4* yr = (uint4*)(g_y + (size_t)n1 * SH);
        yr[0] = u0; yr[1] = u1;
    }
    if (v2) {
        float* pr = g_p + (size_t)n2 * SF;
        float yv[10];
#pragma unroll
        for (int j = 0; j < 5; j++) {
            float lo, hi;
            unpack_f32x2(lo, hi, aP2[j]);
            pr[2 * j] = lo; pr[2 * j + 1] = hi;
            unpack_f32x2(yv[2 * j], yv[2 * j + 1], aY2[j]);
        }
        uint4 u0, u1;
        u0.x = pack_h2(yv[0], yv[1]);
        u0.y = pack_h2(yv[2], yv[3]);
        u0.z = pack_h2(yv[4], yv[5]);
        u0.w = pack_h2(yv[6], yv[7]);
        u1.x = pack_h2(yv[8], yv[9]);
        u1.y = pack_h2(1.0f, 0.0f);
        u1.z = 0; u1.w = 0;
        uint4* yr = (uint4*)(g_y + (size_t)n2 * SH);
        yr[0] = u0; yr[1] = u1;
    }
}

// ---------------------------------------------------------------------------
// K2: layer-1 edge scatter fp16 (2 REDs/edge), 4 edges per thread. PDL entry.
// ---------------------------------------------------------------------------
__global__ void k_edge_scatter1(const int* __restrict__ src, const int* __restrict__ dst,
                                const __half* __restrict__ msg, __half* __restrict__ acc) {
    cudaGridDependencySynchronize();
    int t = blockIdx.x * blockDim.x + threadIdx.x;   // t in [0, EE/4)
    int4 s4 = ((const int4*)src)[t];
    int4 d4 = ((const int4*)dst)[t];
    int ss[4] = {s4.x, s4.y, s4.z, s4.w};
    int dd[4] = {d4.x, d4.y, d4.z, d4.w};

    uint4 a[4]; uint2 b[4];
#pragma unroll
    for (int k = 0; k < 4; k++) {
        const uint4* v = (const uint4*)(msg + (size_t)ss[k] * SH);
        a[k] = v[0];
        b[k] = ((const uint2*)v)[2];
    }
#pragma unroll
    for (int k = 0; k < 4; k++) {
        __half* o = acc + (size_t)dd[k] * SH;
        red_add_v4_h2(o,     a[k].x, a[k].y, a[k].z, a[k].w);
        red_add_v2_h2(o + 8, b[k].x, b[k].y);
    }
}

// ---------------------------------------------------------------------------
// K3: h = relu(p + s1/deg); qω = h·(W2a@Wfc); zω = h·(W2b@Wfc). PDL entry.
// ---------------------------------------------------------------------------
__global__ void k3_layer2in(const float* __restrict__ W2, const float* __restrict__ Wfc) {
    cudaGridDependencySynchronize();
    __shared__ float sWa[10], sWb[10];
    if (threadIdx.x < 20) {
        int k = threadIdx.x;            // row of W2 [20 x 10]
        float v = 0.f;
#pragma unroll
        for (int j = 0; j < 10; j++) v += W2[k * 10 + j] * Wfc[j];
        if (k < 10) sWa[k] = v; else sWb[k - 10] = v;
    }
    __syncthreads();

    int n = blockIdx.x * blockDim.x + threadIdx.x;
    if (n >= NN) return;

    const float* pr = g_p + (size_t)n * SF;
    const uint4* sv = (const uint4*)(g_s1 + (size_t)n * SH);
    uint4 a = sv[0];
    uint2 b = ((const uint2*)sv)[2];

    float s[12];
    {
        float2 t;
        t = __half22float2(*(__half2*)&a.x); s[0] = t.x; s[1] = t.y;
        t = __half22float2(*(__half2*)&a.y); s[2] = t.x; s[3] = t.y;
        t = __half22float2(*(__half2*)&a.z); s[4] = t.x; s[5] = t.y;
        t = __half22float2(*(__half2*)&a.w); s[6] = t.x; s[7] = t.y;
        t = __half22float2(*(__half2*)&b.x); s[8] = t.x; s[9] = t.y;
        t = __half22float2(*(__half2*)&b.y); s[10] = t.x; s[11] = t.y;
    }
    float inv = 1.f / fmaxf(s[10], 1.f);

    float qw = 0.f, zw = 0.f;
#pragma unroll
    for (int j = 0; j < 10; j++) {
        float h = fmaxf(pr[j] + s[j] * inv, 0.f);
        qw += h * sWa[j];
        zw += h * sWb[j];
    }

    g_zw[n] = zw;
    g_qi[n] = make_float2(qw, inv);
}

// ---------------------------------------------------------------------------
// K4: layer-2 edge scatter — ONE scalar fp32 RED per edge to a PRIVATE sector.
// PDL entry.
// ---------------------------------------------------------------------------
__global__ void k_edge_scatter2(const int* __restrict__ src, const int* __restrict__ dst) {
    cudaGridDependencySynchronize();
    int t = blockIdx.x * blockDim.x + threadIdx.x;   // t in [0, EE/4)
    int4 s4 = ((const int4*)src)[t];
    int4 d4 = ((const int4*)dst)[t];
    float v0 = g_zw[s4.x];
    float v1 = g_zw[s4.y];
    float v2 = g_zw[s4.z];
    float v3 = g_zw[s4.w];
    red_add_f32(&g_s2w[(size_t)d4.x * SW], v0);
    red_add_f32(&g_s2w[(size_t)d4.y * SW], v1);
    red_add_f32(&g_s2w[(size_t)d4.z * SW], v2);
    red_add_f32(&g_s2w[(size_t)d4.w * SW], v3);
}

// ---------------------------------------------------------------------------
// K5 (fused with head): h2ω = qω + s2ω/deg; segmented warp-reduce over sorted
// batch; head lanes RED into g_g[b]. Last block computes the sigmoid outputs.
// PDL entry.
// ---------------------------------------------------------------------------
__global__ void k5_pool_head(const int* __restrict__ batch, float* __restrict__ out) {
    cudaGridDependencySynchronize();
    int n = blockIdx.x * blockDim.x + threadIdx.x;
    int lane = threadIdx.x & 31;

    int b = -1;
    float v = 0.f, c = 0.f;
    if (n < NN) {
        float2 qi = g_qi[n];
        v = qi.x + g_s2w[(size_t)n * SW] * qi.y;
        c = 1.f;
        b = batch[n];
    }

    // segmented suffix sum over contiguous equal-b runs (batch sorted)
#pragma unroll
    for (int off = 1; off < 32; off <<= 1) {
        float v2 = __shfl_down_sync(0xffffffff, v, off);
        float c2 = __shfl_down_sync(0xffffffff, c, off);
        int   b2 = __shfl_down_sync(0xffffffff, b, off);
        if (lane + off < 32 && b2 == b) { v += v2; c += c2; }
    }
    int bprev = __shfl_up_sync(0xffffffff, b, 1);
    bool head = (lane == 0) || (bprev != b);
    if (head && b >= 0)
        red_add_v2_f32(&g_g[2 * b], v, c);

    // last-block head: all pool REDs are visible after the counter round-trip
    __threadfence();
    __shared__ bool isLast;
    if (threadIdx.x == 0) {
        unsigned prev = atomicAdd(&g_cnt, 1u);
        isLast = (prev == gridDim.x - 1);
    }
    __syncthreads();
    if (isLast) {
        __threadfence();
        for (int bb = threadIdx.x; bb < BB; bb += blockDim.x) {
            float sum = g_g[2 * bb];
            float cnt = g_g[2 * bb + 1];
            float vv = sum / fmaxf(cnt, 1.f);
            out[bb] = 1.f / (1.f + expf(-vv));
        }
    }
}

// ---------------------------------------------------------------------------
extern "C" void kernel_launch(void* const* d_in, const int* in_sizes, int n_in,
                              void* d_out, int out_size) {
    const float* x     = (const float*)d_in[0];
    const int*   ei    = (const int*)  d_in[1];   // src = ei[0:E), dst = ei[E:2E)
    const int*   batch = (const int*)  d_in[2];
    const float* W1    = (const float*)d_in[3];
    const float* W2    = (const float*)d_in[4];
    const float* Wfc   = (const float*)d_in[5];
    float*       out   = (float*)d_out;

    void *p_y, *p_s1;
    cudaGetSymbolAddress(&p_y,  g_y);
    cudaGetSymbolAddress(&p_s1, g_s1);
    const __half* yv  = (const __half*)p_y;
    __half*       s1v = (__half*)p_s1;

    const int T = 256;

    cudaLaunchAttribute pdl[1];
    pdl[0].id = cudaLaunchAttributeProgrammaticStreamSerialization;
    pdl[0].val.programmaticStreamSerializationAllowed = 1;

    k1_project<<<(NN + 255) / 256, 128>>>(x, W1);

    {
        cudaLaunchConfig_t cfg = {};
        cfg.gridDim = dim3(EE / 4 / T); cfg.blockDim = dim3(T);
        cfg.stream = 0; cfg.attrs = pdl; cfg.numAttrs = 1;
        const int* srcp = ei; const int* dstp = ei + EE;
        cudaLaunchKernelEx(&cfg, k_edge_scatter1, srcp, dstp, yv, s1v);
    }
    {
        cudaLaunchConfig_t cfg = {};
        cfg.gridDim = dim3((NN + 127) / 128); cfg.blockDim = dim3(128);
        cfg.stream = 0; cfg.attrs = pdl; cfg.numAttrs = 1;
        cudaLaunchKernelEx(&cfg, k3_layer2in, W2, Wfc);
    }
    {
        cudaLaunchConfig_t cfg = {};
        cfg.gridDim = dim3(EE / 4 / T); cfg.blockDim = dim3(T);
        cfg.stream = 0; cfg.attrs = pdl; cfg.numAttrs = 1;
        const int* srcp = ei; const int* dstp = ei + EE;
        cudaLaunchKernelEx(&cfg, k_edge_scatter2, srcp, dstp);
    }
    {
        cudaLaunchConfig_t cfg = {};
        cfg.gridDim = dim3((NN + T - 1) / T); cfg.blockDim = dim3(T);
        cfg.stream = 0; cfg.attrs = pdl; cfg.numAttrs = 1;
        cudaLaunchKernelEx(&cfg, k5_pool_head, batch, out);
    }
}

// round 13
// speedup vs baseline: 1.0923x; 1.0431x over previous
#include <cuda_runtime.h>
#include <cuda_fp16.h>
#include <math.h>

#define NN 100000
#define EE 3200000
#define BB 1000
#define FIN 128
#define SH 16         // fp16 row stride (messages/accumulators/p): 32B
#define SW 8          // fp32 stride for s2w: 32B -> private L2 sector per node
#define SWR 12        // padded smem weight row (floats): 48B, 16B-aligned

// Scratch (static device globals: no allocation anywhere)
__device__ __half   g_ph [NN * SH];   // x @ W1[0:128]  (fp16, 10 used)
__device__ __half   g_y  [NN * SH];   // x @ W1[128:256], slot10=1.0 (fp16 message)
__device__ __half   g_s1 [NN * SH];   // edge-accumulated y (slot10 = in-degree)
__device__ float    g_zw [NN];        // scalar layer-2 message  zω = h·(W2b@Wfc)
__device__ float    g_s2w[NN * SW];   // edge-accumulated zω (padded: 1 sector/node)
__device__ float2   g_qi [NN];        // {qω = h·(W2a@Wfc), 1/max(deg,1)}
__device__ float    g_g  [BB * 2];    // {Σ h2ω, node count} per graph
__device__ unsigned g_cnt;            // block-completion counter for fused pool+head

__device__ __forceinline__ void red_add_v2_f32(float* p, float a, float b) {
    asm volatile("red.global.add.v2.f32 [%0], {%1,%2};"
                 :: "l"(p), "f"(a), "f"(b) : "memory");
}
__device__ __forceinline__ void red_add_f32(float* p, float a) {
    asm volatile("red.global.add.f32 [%0], %1;" :: "l"(p), "f"(a) : "memory");
}
__device__ __forceinline__ void red_add_v4_h2(void* p, unsigned a, unsigned b, unsigned c, unsigned d) {
    asm volatile("red.global.add.noftz.v4.f16x2 [%0], {%1,%2,%3,%4};"
                 :: "l"(p), "r"(a), "r"(b), "r"(c), "r"(d) : "memory");
}
__device__ __forceinline__ void red_add_v2_h2(void* p, unsigned a, unsigned b) {
    asm volatile("red.global.add.noftz.v2.f16x2 [%0], {%1,%2};"
                 :: "l"(p), "r"(a), "r"(b) : "memory");
}

__device__ __forceinline__ unsigned pack_h2(float lo, float hi) {
    __half2 h = __floats2half2_rn(lo, hi);
    return *(unsigned*)&h;
}
__device__ __forceinline__ unsigned long long pack_f32x2(float lo, float hi) {
    unsigned long long r;
    asm("mov.b64 %0, {%1,%2};" : "=l"(r) : "f"(lo), "f"(hi));
    return r;
}
__device__ __forceinline__ void unpack_f32x2(float& lo, float& hi, unsigned long long v) {
    asm("mov.b64 {%0,%1}, %2;" : "=f"(lo), "=f"(hi) : "l"(v));
}
__device__ __forceinline__ void fma_f32x2(unsigned long long& acc,
                                          unsigned long long a, unsigned long long b) {
    asm("fma.rn.f32x2 %0, %1, %2, %0;" : "+l"(acc) : "l"(a), "l"(b));
}

// write a 10-value fp16 row (slot10 = tag) as two uint4
__device__ __forceinline__ void store_h16_row(__half* rowp, const float* v, float tag) {
    uint4 u0, u1;
    u0.x = pack_h2(v[0], v[1]);
    u0.y = pack_h2(v[2], v[3]);
    u0.z = pack_h2(v[4], v[5]);
    u0.w = pack_h2(v[6], v[7]);
    u1.x = pack_h2(v[8], v[9]);
    u1.y = pack_h2(tag, 0.0f);
    u1.z = 0; u1.w = 0;
    uint4* r = (uint4*)rowp;
    r[0] = u0; r[1] = u1;
}

// load a 12-half row into floats
__device__ __forceinline__ void load_h12_row(const __half* rowp, float* s) {
    const uint4* rv = (const uint4*)rowp;
    uint4 a = rv[0];
    uint2 b = ((const uint2*)rv)[2];
    float2 t;
    t = __half22float2(*(__half2*)&a.x); s[0] = t.x; s[1] = t.y;
    t = __half22float2(*(__half2*)&a.y); s[2] = t.x; s[3] = t.y;
    t = __half22float2(*(__half2*)&a.z); s[4] = t.x; s[5] = t.y;
    t = __half22float2(*(__half2*)&a.w); s[6] = t.x; s[7] = t.y;
    t = __half22float2(*(__half2*)&b.x); s[8] = t.x; s[9] = t.y;
    t = __half22float2(*(__half2*)&b.y); s[10] = t.x; s[11] = t.y;
}

// ---------------------------------------------------------------------------
// K1: p = x @ W1[0:128,:] (fp16), y = x @ W1[128:256,:] (fp16, slot10=1.0)
// 128 threads/block, 2 nodes/thread -> 391 blocks. Padded-row LDS.128 weights.
// Unroll 4 on the feature-quad loop for deeper LDG MLP.
// Also zeroes g_s1/g_s2w rows, g_g, g_cnt.
// ---------------------------------------------------------------------------
__global__ __launch_bounds__(128) void k1_project(const float* __restrict__ x,
                                                  const float* __restrict__ W1) {
    __shared__ __align__(16) float sW[2 * FIN * SWR];   // 12,288 B
    int tid = threadIdx.x;
    for (int r = tid; r < 2 * FIN; r += 128) {
        const float* wsrc = W1 + r * 10;
        float* wdst = sW + r * SWR;
#pragma unroll
        for (int j = 0; j < 10; j++) wdst[j] = wsrc[j];
        wdst[10] = 0.f; wdst[11] = 0.f;
    }
    __syncthreads();

    int base = blockIdx.x * 256;
    int n1 = base + tid;
    int n2 = n1 + 128;
    bool v1 = (n1 < NN);
    bool v2 = (n2 < NN);

    uint4 zz = {0, 0, 0, 0};
    if (v1) {
        if (n1 == 0) g_cnt = 0u;
        uint4* s1r = (uint4*)(g_s1 + (size_t)n1 * SH);
        s1r[0] = zz; s1r[1] = zz;
        uint4* s2r = (uint4*)(g_s2w + (size_t)n1 * SW);
        s2r[0] = zz; s2r[1] = zz;
        if (n1 < BB) { g_g[2 * n1] = 0.f; g_g[2 * n1 + 1] = 0.f; }
    }
    if (v2) {
        uint4* s1r = (uint4*)(g_s1 + (size_t)n2 * SH);
        s1r[0] = zz; s1r[1] = zz;
        uint4* s2r = (uint4*)(g_s2w + (size_t)n2 * SW);
        s2r[0] = zz; s2r[1] = zz;
        if (n2 < BB) { g_g[2 * n2] = 0.f; g_g[2 * n2 + 1] = 0.f; }
    }
    if (!v1) return;

    unsigned long long aP1[5], aY1[5], aP2[5], aY2[5];
#pragma unroll
    for (int j = 0; j < 5; j++) { aP1[j] = 0ull; aY1[j] = 0ull; aP2[j] = 0ull; aY2[j] = 0ull; }

    const float4* xr1 = (const float4*)(x + (size_t)n1 * FIN);
    const float4* xr2 = (const float4*)(x + (size_t)(v2 ? n2 : n1) * FIN);

#pragma unroll 4
    for (int f4 = 0; f4 < FIN / 4; f4++) {
        float4 xa = xr1[f4];
        float4 xb = xr2[f4];
        float xf1[4] = {xa.x, xa.y, xa.z, xa.w};
        float xf2[4] = {xb.x, xb.y, xb.z, xb.w};
#pragma unroll
        for (int k = 0; k < 4; k++) {
            int f = f4 * 4 + k;
            const ulonglong2* wpv = (const ulonglong2*)&sW[f * SWR];
            ulonglong2 wpA = wpv[0];
            ulonglong2 wpB = wpv[1];
            unsigned long long wpC = *(const unsigned long long*)&sW[f * SWR + 8];
            const ulonglong2* wyv = (const ulonglong2*)&sW[(FIN + f) * SWR];
            ulonglong2 wyA = wyv[0];
            ulonglong2 wyB = wyv[1];
            unsigned long long wyC = *(const unsigned long long*)&sW[(FIN + f) * SWR + 8];

            unsigned long long b1 = pack_f32x2(xf1[k], xf1[k]);
            unsigned long long b2 = pack_f32x2(xf2[k], xf2[k]);

            fma_f32x2(aP1[0], b1, wpA.x); fma_f32x2(aP1[1], b1, wpA.y);
            fma_f32x2(aP1[2], b1, wpB.x); fma_f32x2(aP1[3], b1, wpB.y);
            fma_f32x2(aP1[4], b1, wpC);
            fma_f32x2(aY1[0], b1, wyA.x); fma_f32x2(aY1[1], b1, wyA.y);
            fma_f32x2(aY1[2], b1, wyB.x); fma_f32x2(aY1[3], b1, wyB.y);
            fma_f32x2(aY1[4], b1, wyC);

            fma_f32x2(aP2[0], b2, wpA.x); fma_f32x2(aP2[1], b2, wpA.y);
            fma_f32x2(aP2[2], b2, wpB.x); fma_f32x2(aP2[3], b2, wpB.y);
            fma_f32x2(aP2[4], b2, wpC);
            fma_f32x2(aY2[0], b2, wyA.x); fma_f32x2(aY2[1], b2, wyA.y);
            fma_f32x2(aY2[2], b2, wyB.x); fma_f32x2(aY2[3], b2, wyB.y);
            fma_f32x2(aY2[4], b2, wyC);
        }
    }

    {
        float pv[10], yv[10];
#pragma unroll
        for (int j = 0; j < 5; j++) {
            unpack_f32x2(pv[2 * j], pv[2 * j + 1], aP1[j]);
            unpack_f32x2(yv[2 * j], yv[2 * j + 1], aY1[j]);
        }
        store_h16_row(g_ph + (size_t)n1 * SH, pv, 0.0f);
        store_h16_row(g_y  + (size_t)n1 * SH, yv, 1.0f);   // degree carrier
    }
    if (v2) {
        float pv[10], yv[10];
#pragma unroll
        for (int j = 0; j < 5; j++) {
            unpack_f32x2(pv[2 * j], pv[2 * j + 1], aP2[j]);
            unpack_f32x2(yv[2 * j], yv[2 * j + 1], aY2[j]);
        }
        store_h16_row(g_ph + (size_t)n2 * SH, pv, 0.0f);
        store_h16_row(g_y  + (size_t)n2 * SH, yv, 1.0f);
    }
}

// ---------------------------------------------------------------------------
// K2: layer-1 edge scatter fp16 (2 REDs/edge), 4 edges per thread. PDL entry.
// ---------------------------------------------------------------------------
__global__ void k_edge_scatter1(const int* __restrict__ src, const int* __restrict__ dst,
                                const __half* __restrict__ msg, __half* __restrict__ acc) {
    cudaGridDependencySynchronize();
    int t = blockIdx.x * blockDim.x + threadIdx.x;   // t in [0, EE/4)
    int4 s4 = ((const int4*)src)[t];
    int4 d4 = ((const int4*)dst)[t];
    int ss[4] = {s4.x, s4.y, s4.z, s4.w};
    int dd[4] = {d4.x, d4.y, d4.z, d4.w};

    uint4 a[4]; uint2 b[4];
#pragma unroll
    for (int k = 0; k < 4; k++) {
        const uint4* v = (const uint4*)(msg + (size_t)ss[k] * SH);
        a[k] = v[0];
        b[k] = ((const uint2*)v)[2];
    }
#pragma unroll
    for (int k = 0; k < 4; k++) {
        __half* o = acc + (size_t)dd[k] * SH;
        red_add_v4_h2(o,     a[k].x, a[k].y, a[k].z, a[k].w);
        red_add_v2_h2(o + 8, b[k].x, b[k].y);
    }
}

// ---------------------------------------------------------------------------
// K3: h = relu(p + s1/deg); qω = h·(W2a@Wfc); zω = h·(W2b@Wfc). PDL entry.
// p now fp16 (32B row).
// ---------------------------------------------------------------------------
__global__ void k3_layer2in(const float* __restrict__ W2, const float* __restrict__ Wfc) {
    cudaGridDependencySynchronize();
    __shared__ float sWa[10], sWb[10];
    if (threadIdx.x < 20) {
        int k = threadIdx.x;            // row of W2 [20 x 10]
        float v = 0.f;
#pragma unroll
        for (int j = 0; j < 10; j++) v += W2[k * 10 + j] * Wfc[j];
        if (k < 10) sWa[k] = v; else sWb[k - 10] = v;
    }
    __syncthreads();

    int n = blockIdx.x * blockDim.x + threadIdx.x;
    if (n >= NN) return;

    float s[12], p[12];
    load_h12_row(g_s1 + (size_t)n * SH, s);
    load_h12_row(g_ph + (size_t)n * SH, p);
    float inv = 1.f / fmaxf(s[10], 1.f);

    float qw = 0.f, zw = 0.f;
#pragma unroll
    for (int j = 0; j < 10; j++) {
        float h = fmaxf(p[j] + s[j] * inv, 0.f);
        qw += h * sWa[j];
        zw += h * sWb[j];
    }

    g_zw[n] = zw;
    g_qi[n] = make_float2(qw, inv);
}

// ---------------------------------------------------------------------------
// K4: layer-2 edge scatter — ONE scalar fp32 RED per edge to a PRIVATE sector.
// PDL entry.
// ---------------------------------------------------------------------------
__global__ void k_edge_scatter2(const int* __restrict__ src, const int* __restrict__ dst) {
    cudaGridDependencySynchronize();
    int t = blockIdx.x * blockDim.x + threadIdx.x;   // t in [0, EE/4)
    int4 s4 = ((const int4*)src)[t];
    int4 d4 = ((const int4*)dst)[t];
    float v0 = g_zw[s4.x];
    float v1 = g_zw[s4.y];
    float v2 = g_zw[s4.z];
    float v3 = g_zw[s4.w];
    red_add_f32(&g_s2w[(size_t)d4.x * SW], v0);
    red_add_f32(&g_s2w[(size_t)d4.y * SW], v1);
    red_add_f32(&g_s2w[(size_t)d4.z * SW], v2);
    red_add_f32(&g_s2w[(size_t)d4.w * SW], v3);
}

// ---------------------------------------------------------------------------
// K5 (fused with head): h2ω = qω + s2ω/deg; segmented warp-reduce over sorted
// batch; head lanes RED into g_g[b]. Last block computes the sigmoid outputs.
// PDL entry.
// ---------------------------------------------------------------------------
__global__ void k5_pool_head(const int* __restrict__ batch, float* __restrict__ out) {
    cudaGridDependencySynchronize();
    int n = blockIdx.x * blockDim.x + threadIdx.x;
    int lane = threadIdx.x & 31;

    int b = -1;
    float v = 0.f, c = 0.f;
    if (n < NN) {
        float2 qi = g_qi[n];
        v = qi.x + g_s2w[(size_t)n * SW] * qi.y;
        c = 1.f;
        b = batch[n];
    }

    // segmented suffix sum over contiguous equal-b runs (batch sorted)
#pragma unroll
    for (int off = 1; off < 32; off <<= 1) {
        float v2 = __shfl_down_sync(0xffffffff, v, off);
        float c2 = __shfl_down_sync(0xffffffff, c, off);
        int   b2 = __shfl_down_sync(0xffffffff, b, off);
        if (lane + off < 32 && b2 == b) { v += v2; c += c2; }
    }
    int bprev = __shfl_up_sync(0xffffffff, b, 1);
    bool head = (lane == 0) || (bprev != b);
    if (head && b >= 0)
        red_add_v2_f32(&g_g[2 * b], v, c);

    // last-block head: all pool REDs are visible after the counter round-trip
    __threadfence();
    __shared__ bool isLast;
    if (threadIdx.x == 0) {
        unsigned prev = atomicAdd(&g_cnt, 1u);
        isLast = (prev == gridDim.x - 1);
    }
    __syncthreads();
    if (isLast) {
        __threadfence();
        for (int bb = threadIdx.x; bb < BB; bb += blockDim.x) {
            float sum = g_g[2 * bb];
            float cnt = g_g[2 * bb + 1];
            float vv = sum / fmaxf(cnt, 1.f);
            out[bb] = 1.f / (1.f + expf(-vv));
        }
    }
}

// ---------------------------------------------------------------------------
extern "C" void kernel_launch(void* const* d_in, const int* in_sizes, int n_in,
                              void* d_out, int out_size) {
    const float* x     = (const float*)d_in[0];
    const int*   ei    = (const int*)  d_in[1];   // src = ei[0:E), dst = ei[E:2E)
    const int*   batch = (const int*)  d_in[2];
    const float* W1    = (const float*)d_in[3];
    const float* W2    = (const float*)d_in[4];
    const float* Wfc   = (const float*)d_in[5];
    float*       out   = (float*)d_out;

    void *p_y, *p_s1;
    cudaGetSymbolAddress(&p_y,  g_y);
    cudaGetSymbolAddress(&p_s1, g_s1);
    const __half* yv  = (const __half*)p_y;
    __half*       s1v = (__half*)p_s1;

    const int T = 256;

    cudaLaunchAttribute pdl[1];
    pdl[0].id = cudaLaunchAttributeProgrammaticStreamSerialization;
    pdl[0].val.programmaticStreamSerializationAllowed = 1;

    k1_project<<<(NN + 255) / 256, 128>>>(x, W1);

    {
        cudaLaunchConfig_t cfg = {};
        cfg.gridDim = dim3(EE / 4 / T); cfg.blockDim = dim3(T);
        cfg.stream = 0; cfg.attrs = pdl; cfg.numAttrs = 1;
        const int* srcp = ei; const int* dstp = ei + EE;
        cudaLaunchKernelEx(&cfg, k_edge_scatter1, srcp, dstp, yv, s1v);
    }
    {
        cudaLaunchConfig_t cfg = {};
        cfg.gridDim = dim3((NN + 127) / 128); cfg.blockDim = dim3(128);
        cfg.stream = 0; cfg.attrs = pdl; cfg.numAttrs = 1;
        cudaLaunchKernelEx(&cfg, k3_layer2in, W2, Wfc);
    }
    {
        cudaLaunchConfig_t cfg = {};
        cfg.gridDim = dim3(EE / 4 / T); cfg.blockDim = dim3(T);
        cfg.stream = 0; cfg.attrs = pdl; cfg.numAttrs = 1;
        const int* srcp = ei; const int* dstp = ei + EE;
        cudaLaunchKernelEx(&cfg, k_edge_scatter2, srcp, dstp);
    }
    {
        cudaLaunchConfig_t cfg = {};
        cfg.gridDim = dim3((NN + T - 1) / T); cfg.blockDim = dim3(T);
        cfg.stream = 0; cfg.attrs = pdl; cfg.numAttrs = 1;
        cudaLaunchKernelEx(&cfg, k5_pool_head, batch, out);
    }
}